// round 5
// baseline (speedup 1.0000x reference)
#include <cuda_runtime.h>

// Problem: x[128,3,16,64,64] (*) w[24,3,3,3,3] VALID -> +bias -> min over depth(14) -> softmax over 24 ch
// out: [128,24,62,62] fp32

#define THREADS 192
#define NOC 4    // output channels per thread (6 oc-groups x 4 = 24)
#define NPAIR 4  // f32x2 output pairs per thread (8 pixels)

typedef unsigned long long ull;

__device__ __forceinline__ ull ffma2(ull a, ull b, ull c) {
    ull d;
    asm("fma.rn.f32x2 %0, %1, %2, %3;" : "=l"(d) : "l"(a), "l"(b), "l"(c));
    return d;
}

__device__ __forceinline__ ull min2(ull a, ull b) {
    float alo = __uint_as_float((unsigned)a);
    float ahi = __uint_as_float((unsigned)(a >> 32));
    float blo = __uint_as_float((unsigned)b);
    float bhi = __uint_as_float((unsigned)(b >> 32));
    float lo = fminf(alo, blo), hi = fminf(ahi, bhi);
    return ((ull)__float_as_uint(hi) << 32) | (ull)__float_as_uint(lo);
}

// shared layout (floats):
//   wsm    [27 taps][6 ocg][12 pairs] : 3888   (pairs in order oc0:kw0,kw1,kw2, oc1:..., 16B-load friendly)
//   bdup   [24][2]                    : 48
//   ring   [4][2592]                  : 10368  per slot: sA[3*6][72] then sB[3*6][72] (sB = +1 shifted)
//   minbuf [24][256]                  : 6144
#define SM_WSM    0
#define SM_BDUP   3888
#define SM_RING   3936
#define SM_MINBUF 14304
#define SM_TOTAL  20448   // floats -> 81792 bytes

__global__ __launch_bounds__(THREADS, 2)
void conv3d_min_softmax_kernel(const float* __restrict__ x,
                               const float* __restrict__ wgt,
                               const float* __restrict__ bias,
                               float* __restrict__ out)
{
    extern __shared__ float smem[];
    float* wsm    = smem + SM_WSM;
    float* bdup   = smem + SM_BDUP;
    float* ring   = smem + SM_RING;
    float* minbuf = smem + SM_MINBUF;

    const int tid = threadIdx.x;
    const int b   = blockIdx.y;       // 0..127
    const int r0  = blockIdx.x * 4;   // output row tile base, 0..60

    // ---- stage weights: per tap, 24 oc x 3 kw as duplicated f32x2 pairs ----
    // pair slot within tap = ocg*12 + (oc%4)*3 + kw
    for (int i = tid; i < 1944; i += THREADS) {
        int tap = i / 72, r72 = i % 72;
        int ocg = r72 / 12, rem12 = r72 % 12;
        int j = rem12 / 3, kw = rem12 % 3;
        int oc = ocg * 4 + j;
        float v = wgt[oc * 81 + tap * 3 + kw];
        wsm[2 * i] = v; wsm[2 * i + 1] = v;
    }
    if (tid < 24) { bdup[2 * tid] = bias[tid]; bdup[2 * tid + 1] = bias[tid]; }

    // ---- zero ring pads (cols >= 64 of sA, cols >= 63 of sB) ----
    for (int i = tid; i < 4 * 18; i += THREADS) {
        float* a = ring + (i / 18) * 2592 + (i % 18) * 72;
        #pragma unroll
        for (int c = 64; c < 72; ++c) a[c] = 0.f;
        float* bb = a + 1296;
        #pragma unroll
        for (int c = 63; c < 72; ++c) bb[c] = 0.f;
    }

    const float* xb = x + (size_t)b * (3 * 16 * 4096);

    // ---- prologue: slices 0..2 direct to ring ----
    for (int s = 0; s < 3; ++s) {
        #pragma unroll
        for (int k = 0; k < 6; ++k) {
            int i = tid + k * THREADS;              // 0..1151 (3*6*64)
            int cin = i / 384, rem = i % 384;
            int row = rem >> 6, w = rem & 63;
            int gr = min(r0 + row, 63);
            float v = xb[((cin * 16 + s) << 12) + (gr << 6) + w];
            float* base = ring + s * 2592 + (cin * 6 + row) * 72;
            base[w] = v;
            if (w) base[1296 + w - 1] = v;
        }
    }
    // stage slice 3 into regs
    float stg[6];
    #pragma unroll
    for (int k = 0; k < 6; ++k) {
        int i = tid + k * THREADS;
        int cin = i / 384, rem = i % 384;
        int row = rem >> 6, w = rem & 63;
        int gr = min(r0 + row, 63);
        stg[k] = xb[((cin * 16 + 3) << 12) + (gr << 6) + w];
    }
    __syncthreads();

    const int ocg = tid >> 5;            // 0..5 (whole warp = one oc-group -> weight broadcast)
    const int g   = tid & 31;            // pixel group
    const int r   = g >> 3;              // tile row 0..3
    const int w0  = (g & 7) * 8;         // pixel base 0..56 (8 pixels = 4 pairs)
    const int oc0 = ocg * NOC;

    const ull INF2 = 0x7F8000007F800000ULL;
    ull mn[NOC][NPAIR];
    #pragma unroll
    for (int j = 0; j < NOC; ++j)
        #pragma unroll
        for (int p = 0; p < NPAIR; ++p) mn[j][p] = INF2;

    #pragma unroll 1
    for (int d = 0; d < 14; ++d) {
        ull acc[NOC][NPAIR];
        #pragma unroll
        for (int j = 0; j < NOC; ++j) {
            ull bj = *reinterpret_cast<const ull*>(bdup + 2 * (oc0 + j));
            #pragma unroll
            for (int p = 0; p < NPAIR; ++p) acc[j][p] = bj;
        }

        #pragma unroll
        for (int cin = 0; cin < 3; ++cin) {
            #pragma unroll 1
            for (int kd = 0; kd < 3; ++kd) {
                const float* slot = ring + ((d + kd) & 3) * 2592 + (cin * 6 + r) * 72 + w0;
                const int tap0 = cin * 9 + kd * 3;
                #pragma unroll
                for (int kh = 0; kh < 3; ++kh) {
                    const float* rowA = slot + kh * 72;
                    const float* rowB = rowA + 1296;
                    // pixel pairs (all 16B/8B aligned: w0 is a multiple of 8 floats)
                    ulonglong2 a0 = *reinterpret_cast<const ulonglong2*>(rowA);      // p01,p23
                    ulonglong2 a1 = *reinterpret_cast<const ulonglong2*>(rowA + 4);  // p45,p67
                    ull        p89 = *reinterpret_cast<const ull*>(rowA + 8);
                    ulonglong2 b0 = *reinterpret_cast<const ulonglong2*>(rowB);      // p12,p34
                    ulonglong2 b1 = *reinterpret_cast<const ulonglong2*>(rowB + 4);  // p56,p78
                    ull pk0[NPAIR] = { a0.x, a0.y, a1.x, a1.y };   // kw=0 inputs
                    ull pk1[NPAIR] = { b0.x, b0.y, b1.x, b1.y };   // kw=1 inputs
                    ull pk2[NPAIR] = { a0.y, a1.x, a1.y, p89 };    // kw=2 inputs

                    // weights: 12 pairs for this (tap, ocg), 6 x LDS.128 broadcast
                    const float* wp = wsm + ((tap0 + kh) * 6 + ocg) * 24;
                    ulonglong2 v0 = *reinterpret_cast<const ulonglong2*>(wp);
                    ulonglong2 v1 = *reinterpret_cast<const ulonglong2*>(wp + 4);
                    ulonglong2 v2 = *reinterpret_cast<const ulonglong2*>(wp + 8);
                    ulonglong2 v3 = *reinterpret_cast<const ulonglong2*>(wp + 12);
                    ulonglong2 v4 = *reinterpret_cast<const ulonglong2*>(wp + 16);
                    ulonglong2 v5 = *reinterpret_cast<const ulonglong2*>(wp + 20);
                    ull w[NOC][3] = {
                        { v0.x, v0.y, v1.x },
                        { v1.y, v2.x, v2.y },
                        { v3.x, v3.y, v4.x },
                        { v4.y, v5.x, v5.y },
                    };

                    #pragma unroll
                    for (int j = 0; j < NOC; ++j)
                        #pragma unroll
                        for (int p = 0; p < NPAIR; ++p) {
                            acc[j][p] = ffma2(w[j][0], pk0[p], acc[j][p]);
                            acc[j][p] = ffma2(w[j][1], pk1[p], acc[j][p]);
                            acc[j][p] = ffma2(w[j][2], pk2[p], acc[j][p]);
                        }
                }
            }
        }
        #pragma unroll
        for (int j = 0; j < NOC; ++j)
            #pragma unroll
            for (int p = 0; p < NPAIR; ++p) mn[j][p] = min2(mn[j][p], acc[j][p]);

        __syncthreads();  // everyone done reading slot (d+3)&3 (held slice d-1)
        if (d + 3 <= 15) {
            float* sl = ring + ((d + 3) & 3) * 2592;
            #pragma unroll
            for (int k = 0; k < 6; ++k) {
                int i = tid + k * THREADS;
                int cin = i / 384, rem = i % 384;
                int row = rem >> 6, w = rem & 63;
                float* base = sl + (cin * 6 + row) * 72;
                base[w] = stg[k];
                if (w) base[1296 + w - 1] = stg[k];
            }
        }
        if (d + 4 <= 15) {
            #pragma unroll
            for (int k = 0; k < 6; ++k) {
                int i = tid + k * THREADS;
                int cin = i / 384, rem = i % 384;
                int row = rem >> 6, w = rem & 63;
                int gr = min(r0 + row, 63);
                stg[k] = xb[((cin * 16 + d + 4) << 12) + (gr << 6) + w];
            }
        }
        __syncthreads();
    }

    // ---- exchange per-channel mins via smem ----
    #pragma unroll
    for (int j = 0; j < NOC; ++j) {
        float* base = minbuf + (oc0 + j) * 256 + r * 64 + w0;
        ulonglong2 m01; m01.x = mn[j][0]; m01.y = mn[j][1];
        ulonglong2 m23; m23.x = mn[j][2]; m23.y = mn[j][3];
        *reinterpret_cast<ulonglong2*>(base)     = m01;
        *reinterpret_cast<ulonglong2*>(base + 4) = m23;
    }
    __syncthreads();

    // ---- softmax over 24 channels per pixel ----
    for (int p = tid; p < 256; p += THREADS) {
        float m = -3.402823466e38f;
        #pragma unroll
        for (int oc = 0; oc < 24; ++oc) m = fmaxf(m, minbuf[oc * 256 + p]);
        float s = 0.f;
        #pragma unroll
        for (int oc = 0; oc < 24; ++oc) {
            float e = __expf(minbuf[oc * 256 + p] - m);
            minbuf[oc * 256 + p] = e;
            s += e;
        }
        float rinv = 1.0f / s;
        #pragma unroll
        for (int oc = 0; oc < 24; ++oc) minbuf[oc * 256 + p] *= rinv;
    }
    __syncthreads();

    // ---- coalesced store ----
    float* ob = out + (size_t)b * (24 * 62 * 62);
    for (int i = tid; i < 24 * 256; i += THREADS) {
        int oc = i >> 8, rem = i & 255;
        int row = rem >> 6, w = rem & 63;
        int oh = r0 + row;
        if (w < 62 && oh < 62)
            ob[(oc * 62 + oh) * 62 + w] = minbuf[i];
    }
}

extern "C" void kernel_launch(void* const* d_in, const int* in_sizes, int n_in,
                              void* d_out, int out_size) {
    const float* x    = (const float*)d_in[0];
    const float* wgt  = (const float*)d_in[1];
    const float* bias = (const float*)d_in[2];
    float* out = (float*)d_out;

    cudaFuncSetAttribute(conv3d_min_softmax_kernel,
                         cudaFuncAttributeMaxDynamicSharedMemorySize,
                         SM_TOTAL * (int)sizeof(float));
    dim3 grid(16, 128);  // 16 row-tiles x 128 batches
    conv3d_min_softmax_kernel<<<grid, THREADS, SM_TOTAL * sizeof(float)>>>(x, wgt, bias, out);
}

// round 7
// speedup vs baseline: 1.1368x; 1.1368x over previous
#include <cuda_runtime.h>

// x[128,3,16,64,64] (*) w[24,3,3,3,3] VALID -> +bias -> min over depth(14) -> softmax over 24ch
// out [128,24,62,62] fp32
//
// Strategy: loop over 16 input slices with 3 rolling accumulator generations
// (output depths d=s, s-1, s-2). f32x2 pairs packed over (oc,oc+1); pixels come
// from a duplicated-pixel smem image (aligned LDS.128), weights broadcast.

#define THREADS 192
typedef unsigned long long ull;

__device__ __forceinline__ ull ffma2(ull a, ull b, ull c) {
    ull d;
    asm("fma.rn.f32x2 %0, %1, %2, %3;" : "=l"(d) : "l"(a), "l"(b), "l"(c));
    return d;
}
__device__ __forceinline__ ull min2(ull a, ull b) {
    float alo = __uint_as_float((unsigned)a), ahi = __uint_as_float((unsigned)(a >> 32));
    float blo = __uint_as_float((unsigned)b), bhi = __uint_as_float((unsigned)(b >> 32));
    float lo = fminf(alo, blo), hi = fminf(ahi, bhi);
    return ((ull)__float_as_uint(hi) << 32) | (ull)__float_as_uint(lo);
}

// smem layout (floats):
//   wsm  [27 taps][3 thirds][24]          : 1944  (pairs (oc2j,oc2j+1), kw-major)
//   ring 3 slots x [18 rows][132]         : 7128  (pixel-duplicated: col c stored at 2c,2c+1)
//   minbuf [256 pixels][26]               : 6656  (running min, then softmax result)
#define SM_WSM   0
#define SM_RING  1952
#define SM_MIN   9080
#define SM_TOTAL 15736   // floats = 62944 bytes

__device__ __forceinline__ void applyw(const float* __restrict__ wp, ull (&A)[16], const ull (&pp)[6]) {
    ulonglong2 v0 = *(const ulonglong2*)(wp);
    ulonglong2 v1 = *(const ulonglong2*)(wp + 4);
    ulonglong2 v2 = *(const ulonglong2*)(wp + 8);
    ulonglong2 v3 = *(const ulonglong2*)(wp + 12);
    ulonglong2 v4 = *(const ulonglong2*)(wp + 16);
    ulonglong2 v5 = *(const ulonglong2*)(wp + 20);
    ull w[3][4] = { { v0.x, v0.y, v1.x, v1.y },
                    { v2.x, v2.y, v3.x, v3.y },
                    { v4.x, v4.y, v5.x, v5.y } };
    #pragma unroll
    for (int kw = 0; kw < 3; ++kw)
        #pragma unroll
        for (int jp = 0; jp < 4; ++jp)
            #pragma unroll
            for (int px = 0; px < 4; ++px)
                A[jp * 4 + px] = ffma2(w[kw][jp], pp[px + kw], A[jp * 4 + px]);
}

// A0 <- kd=0 taps, A1 <- kd=1, A2 <- kd=2 (caller rotates roles)
template<bool K0, bool K1, bool K2>
__device__ __forceinline__ void slice_pass(const float* __restrict__ slot,
                                           const float* __restrict__ wsm,
                                           int third, int rwoff,
                                           ull (&A0)[16], ull (&A1)[16], ull (&A2)[16])
{
    #pragma unroll 1
    for (int ck = 0; ck < 9; ++ck) {          // ck = cin*3 + kh
        int cin = ck / 3, kh = ck % 3;
        const float* pr = slot + (cin * 6 + kh) * 132 + rwoff;   // rwoff = r*132 + 2*w0
        ulonglong2 P0 = *(const ulonglong2*)pr;
        ulonglong2 P1 = *(const ulonglong2*)(pr + 4);
        ulonglong2 P2 = *(const ulonglong2*)(pr + 8);
        ull pp[6] = { P0.x, P0.y, P1.x, P1.y, P2.x, P2.y };
        const float* wb = wsm + ((cin * 9 + kh) * 3 + third) * 24;
        if (K0) applyw(wb,       A0, pp);
        if (K1) applyw(wb + 216, A1, pp);     // kd=1: +3 taps * 3 thirds * 24
        if (K2) applyw(wb + 432, A2, pp);     // kd=2
    }
}

template<bool FIRST>
__device__ __forceinline__ void fold(float* __restrict__ minbuf, int pbase, int oc0,
                                     ull (&A)[16], const ull (&bini)[4]) {
    #pragma unroll
    for (int jp = 0; jp < 4; ++jp)
        #pragma unroll
        for (int px = 0; px < 4; ++px) {
            ull* q = (ull*)(minbuf + (pbase + px) * 26 + oc0 + 2 * jp);
            if (FIRST) *q = A[jp * 4 + px];
            else       *q = min2(*q, A[jp * 4 + px]);
            A[jp * 4 + px] = bini[jp];
        }
}

__device__ __forceinline__ void stage_ldg(const float* __restrict__ xb, int r0, int tid,
                                          int s, float (&stg)[6]) {
    #pragma unroll
    for (int k = 0; k < 6; ++k) {
        int i = tid + k * THREADS;                 // 0..1151 = 3cin*6row*64w
        int cin = i / 384, rem = i % 384;
        int row = rem >> 6, w = rem & 63;
        int gr = min(r0 + row, 63);
        stg[k] = xb[((cin * 16 + s) << 12) + (gr << 6) + w];
    }
}
__device__ __forceinline__ void stage_sts(float* __restrict__ ring, int slot, int tid,
                                          const float (&stg)[6]) {
    float* sl = ring + slot * 2376;
    #pragma unroll
    for (int k = 0; k < 6; ++k) {
        int i = tid + k * THREADS;
        int cin = i / 384, rem = i % 384;
        int row = rem >> 6, w = rem & 63;
        unsigned u = __float_as_uint(stg[k]);
        ull v2 = ((ull)u << 32) | (ull)u;          // duplicated pixel pair
        *(ull*)(sl + (cin * 6 + row) * 132 + 2 * w) = v2;
    }
}

__global__ __launch_bounds__(THREADS, 2)
void conv3d_min_softmax_kernel(const float* __restrict__ x,
                               const float* __restrict__ wgt,
                               const float* __restrict__ bias,
                               float* __restrict__ out)
{
    extern __shared__ float smem[];
    float* wsm    = smem + SM_WSM;
    float* ring   = smem + SM_RING;
    float* minbuf = smem + SM_MIN;

    const int tid = threadIdx.x;
    const int b   = blockIdx.y;
    const int r0  = blockIdx.x * 4;

    // ---- stage weights: [tap][third][ (kw*4+jp)*2+lane ] ----
    for (int i = tid; i < 1944; i += THREADS) {
        int tap = i / 72, rem = i % 72;
        int third_ = rem / 24, f = rem % 24;
        int p = f >> 1, lane = f & 1;
        int kw = p >> 2, jp = p & 3;
        int oc = third_ * 8 + jp * 2 + lane;
        wsm[i] = wgt[oc * 81 + tap * 3 + kw];
    }
    // zero dup-image pads (cols 128..131 of each row, all 3 slots)
    for (int i = tid; i < 216; i += THREADS) {
        int slot = i / 72, rem = i % 72;
        int row = rem >> 2, c = rem & 3;
        ring[slot * 2376 + row * 132 + 128 + c] = 0.f;
    }

    const float* xb = x + (size_t)b * (3 * 16 * 4096);
    float stg[6];

    // prologue: slices 0,1 to slots 0,1; prefetch slice 2
    stage_ldg(xb, r0, tid, 0, stg); stage_sts(ring, 0, tid, stg);
    stage_ldg(xb, r0, tid, 1, stg); stage_sts(ring, 1, tid, stg);
    stage_ldg(xb, r0, tid, 2, stg);
    __syncthreads();

    const int third = tid / 64;          // warp-uniform -> weight broadcast
    const int g     = tid % 64;
    const int r     = g >> 4;            // tile row 0..3
    const int w0    = (g & 15) * 4;      // 4 pixels per thread
    const int oc0   = third * 8;
    const int rwoff = r * 132 + 2 * w0;
    const int pbase = r * 64 + w0;

    ull bini[4];
    #pragma unroll
    for (int jp = 0; jp < 4; ++jp)
        bini[jp] = *(const ull*)(bias + oc0 + 2 * jp);

    ull A[3][16];
    #pragma unroll
    for (int gix = 0; gix < 3; ++gix)
        #pragma unroll
        for (int t = 0; t < 16; ++t) A[gix][t] = bini[t >> 2];

    const float* slot0 = ring;
    const float* slot1 = ring + 2376;
    const float* slot2 = ring + 4752;

    // s=0: kd0 -> A0
    slice_pass<true, false, false>(slot0, wsm, third, rwoff, A[0], A[1], A[2]);
    stage_sts(ring, 2, tid, stg); stage_ldg(xb, r0, tid, 3, stg);
    __syncthreads();

    // s=1: kd0 -> A1, kd1 -> A0
    slice_pass<true, true, false>(slot1, wsm, third, rwoff, A[1], A[0], A[2]);
    stage_sts(ring, 0, tid, stg); stage_ldg(xb, r0, tid, 4, stg);
    __syncthreads();

    // s=2: kd0->A2, kd1->A1, kd2->A0; fold d0 (first: plain store)
    slice_pass<true, true, true>(slot2, wsm, third, rwoff, A[2], A[1], A[0]);
    fold<true>(minbuf, pbase, oc0, A[0], bini);
    stage_sts(ring, 1, tid, stg); stage_ldg(xb, r0, tid, 5, stg);
    __syncthreads();

    // main: s = st, st+1, st+2 for st = 3,6,9  (slices 3..11)
    #pragma unroll 1
    for (int st = 3; st <= 9; st += 3) {
        // s=st  (slot 0): kd0->A0, kd1->A2, kd2->A1, fold d=st-2
        slice_pass<true, true, true>(slot0, wsm, third, rwoff, A[0], A[2], A[1]);
        fold<false>(minbuf, pbase, oc0, A[1], bini);
        stage_sts(ring, 2, tid, stg); stage_ldg(xb, r0, tid, st + 3, stg);
        __syncthreads();
        // s=st+1 (slot 1): kd0->A1, kd1->A0, kd2->A2
        slice_pass<true, true, true>(slot1, wsm, third, rwoff, A[1], A[0], A[2]);
        fold<false>(minbuf, pbase, oc0, A[2], bini);
        stage_sts(ring, 0, tid, stg); stage_ldg(xb, r0, tid, st + 4, stg);
        __syncthreads();
        // s=st+2 (slot 2): kd0->A2, kd1->A1, kd2->A0
        slice_pass<true, true, true>(slot2, wsm, third, rwoff, A[2], A[1], A[0]);
        fold<false>(minbuf, pbase, oc0, A[0], bini);
        stage_sts(ring, 1, tid, stg); stage_ldg(xb, r0, tid, st + 5, stg);
        __syncthreads();
    }

    // s=12 (slot 0): kd0->A0, kd1->A2, kd2->A1, fold d10
    slice_pass<true, true, true>(slot0, wsm, third, rwoff, A[0], A[2], A[1]);
    fold<false>(minbuf, pbase, oc0, A[1], bini);
    stage_sts(ring, 2, tid, stg); stage_ldg(xb, r0, tid, 15, stg);
    __syncthreads();

    // s=13 (slot 1): kd0->A1, kd1->A0, kd2->A2, fold d11
    slice_pass<true, true, true>(slot1, wsm, third, rwoff, A[1], A[0], A[2]);
    fold<false>(minbuf, pbase, oc0, A[2], bini);
    stage_sts(ring, 0, tid, stg);   // slice 15 -> slot 0
    __syncthreads();

    // s=14 (slot 2): kd1->A1 (d13), kd2->A0 (d12), fold d12
    slice_pass<false, true, true>(slot2, wsm, third, rwoff, A[2], A[1], A[0]);
    fold<false>(minbuf, pbase, oc0, A[0], bini);
    __syncthreads();

    // s=15 (slot 0): kd2->A1 (d13), fold d13
    slice_pass<false, false, true>(slot0, wsm, third, rwoff, A[2], A[0], A[1]);
    fold<false>(minbuf, pbase, oc0, A[1], bini);
    __syncthreads();

    // ---- softmax over 24 channels per pixel ----
    for (int p = tid; p < 256; p += THREADS) {
        float* row = minbuf + p * 26;
        float m = -3.402823466e38f;
        #pragma unroll
        for (int oc = 0; oc < 24; ++oc) m = fmaxf(m, row[oc]);
        float ssum = 0.f;
        #pragma unroll
        for (int oc = 0; oc < 24; ++oc) {
            float e = __expf(row[oc] - m);
            row[oc] = e;
            ssum += e;
        }
        float rinv = 1.0f / ssum;
        #pragma unroll
        for (int oc = 0; oc < 24; ++oc) row[oc] *= rinv;
    }
    __syncthreads();

    // ---- coalesced store ----
    float* ob = out + (size_t)b * (24 * 62 * 62);
    for (int i = tid; i < 24 * 256; i += THREADS) {
        int oc = i >> 8, pix = i & 255;
        int row = pix >> 6, w = pix & 63;
        int oh = r0 + row;
        if (w < 62 && oh < 62)
            ob[(oc * 62 + oh) * 62 + w] = minbuf[pix * 26 + oc];
    }
}

extern "C" void kernel_launch(void* const* d_in, const int* in_sizes, int n_in,
                              void* d_out, int out_size) {
    const float* x    = (const float*)d_in[0];
    const float* wgt  = (const float*)d_in[1];
    const float* bias = (const float*)d_in[2];
    float* out = (float*)d_out;

    cudaFuncSetAttribute(conv3d_min_softmax_kernel,
                         cudaFuncAttributeMaxDynamicSharedMemorySize,
                         SM_TOTAL * (int)sizeof(float));
    dim3 grid(16, 128);
    conv3d_min_softmax_kernel<<<grid, THREADS, SM_TOTAL * sizeof(float)>>>(x, wgt, bias, out);
}

// round 8
// speedup vs baseline: 1.2033x; 1.0585x over previous
#include <cuda_runtime.h>

// x[128,3,16,64,64] (*) w[24,3,3,3,3] VALID -> +bias -> min over depth(14) -> softmax over 24ch
// out [128,24,62,62] fp32
//
// Rolling 3-generation accumulators over 16 input slices; f32x2 packed over
// (oc,oc+1); pixels from duplicated-pixel smem image (aligned LDS.128).
// This round: 2-row tiles, 4 oc x 4 px per thread, min kept in registers,
// __launch_bounds__(192,3) for 3 blocks/SM (occupancy was the R7 limiter).

#define THREADS 192
typedef unsigned long long ull;

__device__ __forceinline__ ull ffma2(ull a, ull b, ull c) {
    ull d;
    asm("fma.rn.f32x2 %0, %1, %2, %3;" : "=l"(d) : "l"(a), "l"(b), "l"(c));
    return d;
}
__device__ __forceinline__ ull min2(ull a, ull b) {
    float alo = __uint_as_float((unsigned)a), ahi = __uint_as_float((unsigned)(a >> 32));
    float blo = __uint_as_float((unsigned)b), bhi = __uint_as_float((unsigned)(b >> 32));
    float lo = fminf(alo, blo), hi = fminf(ahi, bhi);
    return ((ull)__float_as_uint(hi) << 32) | (ull)__float_as_uint(lo);
}

// smem layout (floats):
//   wsm  [27 taps][6 ocg][12]        : 1944   (2 oc-pairs x 3 kw, kw-major)
//   ring 3 slots x [12 rows][132]    : 4752   (3cin x 4row, pixel-duplicated)
//   minbuf [128 px][26]              : 3328
#define SM_WSM   0
#define SM_RING  1944
#define SM_MIN   6696
#define SM_TOTAL 10024   // floats = 40096 bytes

__device__ __forceinline__ void applyw(const float* __restrict__ wp, ull (&A)[8], const ull (&pp)[6]) {
    ulonglong2 v0 = *(const ulonglong2*)(wp);        // kw0: jp0, jp1
    ulonglong2 v1 = *(const ulonglong2*)(wp + 4);    // kw1
    ulonglong2 v2 = *(const ulonglong2*)(wp + 8);    // kw2
    ull w[3][2] = { { v0.x, v0.y }, { v1.x, v1.y }, { v2.x, v2.y } };
    #pragma unroll
    for (int kw = 0; kw < 3; ++kw)
        #pragma unroll
        for (int jp = 0; jp < 2; ++jp)
            #pragma unroll
            for (int px = 0; px < 4; ++px)
                A[jp * 4 + px] = ffma2(w[kw][jp], pp[px + kw], A[jp * 4 + px]);
}

// A0 <- kd=0 taps, A1 <- kd=1, A2 <- kd=2 (caller rotates roles)
template<bool K0, bool K1, bool K2>
__device__ __forceinline__ void slice_pass(const float* __restrict__ slot,
                                           const float* __restrict__ wsm,
                                           int ocg, int rwoff,
                                           ull (&A0)[8], ull (&A1)[8], ull (&A2)[8])
{
    #pragma unroll 1
    for (int ck = 0; ck < 9; ++ck) {          // ck = cin*3 + kh
        int cin = ck / 3, kh = ck % 3;
        const float* pr = slot + (cin * 4 + kh) * 132 + rwoff;   // rwoff = (r)*132 + 2*w0 folded by caller
        ulonglong2 P0 = *(const ulonglong2*)pr;
        ulonglong2 P1 = *(const ulonglong2*)(pr + 4);
        ulonglong2 P2 = *(const ulonglong2*)(pr + 8);
        ull pp[6] = { P0.x, P0.y, P1.x, P1.y, P2.x, P2.y };
        const float* wb = wsm + ((cin * 9 + kh) * 6 + ocg) * 12;
        if (K0) applyw(wb,       A0, pp);
        if (K1) applyw(wb + 216, A1, pp);     // kd=1: +3 taps * 72
        if (K2) applyw(wb + 432, A2, pp);     // kd=2
    }
}

__device__ __forceinline__ void fold(ull (&mn)[8], ull (&A)[8], const ull (&bini)[2]) {
    #pragma unroll
    for (int t = 0; t < 8; ++t) {
        mn[t] = min2(mn[t], A[t]);
        A[t] = bini[t >> 2];
    }
}

__device__ __forceinline__ void stage_ldg(const float* __restrict__ xb, int r0, int tid,
                                          int s, float (&stg)[4]) {
    #pragma unroll
    for (int k = 0; k < 4; ++k) {
        int i = tid + k * THREADS;                 // 0..767 = 3cin*4row*64w
        int cin = i >> 8, rem = i & 255;
        int row = rem >> 6, w = rem & 63;
        stg[k] = xb[((cin * 16 + s) << 12) + ((r0 + row) << 6) + w];
    }
}
__device__ __forceinline__ void stage_sts(float* __restrict__ ring, int slot, int tid,
                                          const float (&stg)[4]) {
    float* sl = ring + slot * 1584;
    #pragma unroll
    for (int k = 0; k < 4; ++k) {
        int i = tid + k * THREADS;
        int cin = i >> 8, rem = i & 255;
        int row = rem >> 6, w = rem & 63;
        unsigned u = __float_as_uint(stg[k]);
        ull v2 = ((ull)u << 32) | (ull)u;          // duplicated pixel pair
        *(ull*)(sl + (cin * 4 + row) * 132 + 2 * w) = v2;
    }
}

__global__ __launch_bounds__(THREADS, 3)
void conv3d_min_softmax_kernel(const float* __restrict__ x,
                               const float* __restrict__ wgt,
                               const float* __restrict__ bias,
                               float* __restrict__ out)
{
    extern __shared__ float smem[];
    float* wsm    = smem + SM_WSM;
    float* ring   = smem + SM_RING;
    float* minbuf = smem + SM_MIN;

    const int tid = threadIdx.x;
    const int b   = blockIdx.y;
    const int r0  = blockIdx.x * 2;     // 0..60

    // ---- stage weights: [tap][ocg][ (kw*2+jp)*2+lane ] ----
    for (int i = tid; i < 1944; i += THREADS) {
        int tap = i / 72, rem = i % 72;
        int ocg_ = rem / 12, f = rem % 12;
        int p = f >> 1, lane = f & 1;
        int kw = p >> 1, jp = p & 1;
        int oc = ocg_ * 4 + jp * 2 + lane;
        wsm[i] = wgt[oc * 81 + tap * 3 + kw];
    }
    // zero dup-image pads (cols 128..131 of each row, all 3 slots)
    for (int i = tid; i < 144; i += THREADS) {
        int slot = i / 48, rem = i % 48;
        int row = rem >> 2, c = rem & 3;
        ring[slot * 1584 + row * 132 + 128 + c] = 0.f;
    }

    const float* xb = x + (size_t)b * (3 * 16 * 4096);
    float stg[4];

    // prologue: slices 0,1 to slots 0,1; prefetch slice 2
    stage_ldg(xb, r0, tid, 0, stg); stage_sts(ring, 0, tid, stg);
    stage_ldg(xb, r0, tid, 1, stg); stage_sts(ring, 1, tid, stg);
    stage_ldg(xb, r0, tid, 2, stg);
    __syncthreads();

    const int ocg = tid >> 5;            // 0..5, warp-uniform -> weight broadcast
    const int g   = tid & 31;
    const int r   = g >> 4;              // tile row 0..1
    const int w0  = (g & 15) * 4;        // 4 pixels per thread
    const int oc0 = ocg * 4;
    const int rwoff = r * 132 + 2 * w0;
    const int pbase = r * 64 + w0;

    ull bini[2];
    #pragma unroll
    for (int jp = 0; jp < 2; ++jp)
        bini[jp] = *(const ull*)(bias + oc0 + 2 * jp);

    ull A[3][8];
    #pragma unroll
    for (int gix = 0; gix < 3; ++gix)
        #pragma unroll
        for (int t = 0; t < 8; ++t) A[gix][t] = bini[t >> 2];

    const ull INF2 = 0x7F8000007F800000ULL;
    ull mn[8];
    #pragma unroll
    for (int t = 0; t < 8; ++t) mn[t] = INF2;

    const float* slot0 = ring;
    const float* slot1 = ring + 1584;
    const float* slot2 = ring + 3168;

    // s=0: kd0 -> A0
    slice_pass<true, false, false>(slot0, wsm, ocg, rwoff, A[0], A[1], A[2]);
    stage_sts(ring, 2, tid, stg); stage_ldg(xb, r0, tid, 3, stg);
    __syncthreads();

    // s=1: kd0 -> A1, kd1 -> A0
    slice_pass<true, true, false>(slot1, wsm, ocg, rwoff, A[1], A[0], A[2]);
    stage_sts(ring, 0, tid, stg); stage_ldg(xb, r0, tid, 4, stg);
    __syncthreads();

    // s=2: kd0->A2, kd1->A1, kd2->A0; fold d0
    slice_pass<true, true, true>(slot2, wsm, ocg, rwoff, A[2], A[1], A[0]);
    fold(mn, A[0], bini);
    stage_sts(ring, 1, tid, stg); stage_ldg(xb, r0, tid, 5, stg);
    __syncthreads();

    // main: s = st, st+1, st+2 for st = 3,6,9  (slices 3..11)
    #pragma unroll 1
    for (int st = 3; st <= 9; st += 3) {
        slice_pass<true, true, true>(slot0, wsm, ocg, rwoff, A[0], A[2], A[1]);
        fold(mn, A[1], bini);
        stage_sts(ring, 2, tid, stg); stage_ldg(xb, r0, tid, st + 3, stg);
        __syncthreads();

        slice_pass<true, true, true>(slot1, wsm, ocg, rwoff, A[1], A[0], A[2]);
        fold(mn, A[2], bini);
        stage_sts(ring, 0, tid, stg); stage_ldg(xb, r0, tid, st + 4, stg);
        __syncthreads();

        slice_pass<true, true, true>(slot2, wsm, ocg, rwoff, A[2], A[1], A[0]);
        fold(mn, A[0], bini);
        stage_sts(ring, 1, tid, stg); stage_ldg(xb, r0, tid, st + 5, stg);
        __syncthreads();
    }

    // s=12: kd0->A0, kd1->A2, kd2->A1, fold d10
    slice_pass<true, true, true>(slot0, wsm, ocg, rwoff, A[0], A[2], A[1]);
    fold(mn, A[1], bini);
    stage_sts(ring, 2, tid, stg); stage_ldg(xb, r0, tid, 15, stg);
    __syncthreads();

    // s=13: kd0->A1, kd1->A0, kd2->A2, fold d11
    slice_pass<true, true, true>(slot1, wsm, ocg, rwoff, A[1], A[0], A[2]);
    fold(mn, A[2], bini);
    stage_sts(ring, 0, tid, stg);   // slice 15 -> slot 0
    __syncthreads();

    // s=14: kd1->A1 (d13), kd2->A0 (d12), fold d12
    slice_pass<false, true, true>(slot2, wsm, ocg, rwoff, A[2], A[1], A[0]);
    fold(mn, A[0], bini);
    __syncthreads();

    // s=15: kd2->A1 (d13), fold d13
    slice_pass<false, false, true>(slot0, wsm, ocg, rwoff, A[2], A[0], A[1]);
    fold(mn, A[1], bini);

    // ---- write per-thread mins to smem ----
    #pragma unroll
    for (int jp = 0; jp < 2; ++jp)
        #pragma unroll
        for (int px = 0; px < 4; ++px)
            *(ull*)(minbuf + (pbase + px) * 26 + oc0 + 2 * jp) = mn[jp * 4 + px];
    __syncthreads();

    // ---- softmax over 24 channels per pixel (128 pixels) ----
    if (tid < 128) {
        float* row = minbuf + tid * 26;
        float m = -3.402823466e38f;
        #pragma unroll
        for (int oc = 0; oc < 24; ++oc) m = fmaxf(m, row[oc]);
        float ssum = 0.f;
        #pragma unroll
        for (int oc = 0; oc < 24; ++oc) {
            float e = __expf(row[oc] - m);
            row[oc] = e;
            ssum += e;
        }
        float rinv = 1.0f / ssum;
        #pragma unroll
        for (int oc = 0; oc < 24; ++oc) row[oc] *= rinv;
    }
    __syncthreads();

    // ---- coalesced store (rows r0, r0+1 always < 62) ----
    float* ob = out + (size_t)b * (24 * 62 * 62);
    for (int i = tid; i < 24 * 128; i += THREADS) {
        int oc = i >> 7, pix = i & 127;
        int row = pix >> 6, w = pix & 63;
        if (w < 62)
            ob[(oc * 62 + r0 + row) * 62 + w] = minbuf[pix * 26 + oc];
    }
}

extern "C" void kernel_launch(void* const* d_in, const int* in_sizes, int n_in,
                              void* d_out, int out_size) {
    const float* x    = (const float*)d_in[0];
    const float* wgt  = (const float*)d_in[1];
    const float* bias = (const float*)d_in[2];
    float* out = (float*)d_out;

    cudaFuncSetAttribute(conv3d_min_softmax_kernel,
                         cudaFuncAttributeMaxDynamicSharedMemorySize,
                         SM_TOTAL * (int)sizeof(float));
    dim3 grid(31, 128);   // 31 two-row tiles x 128 batches
    conv3d_min_softmax_kernel<<<grid, THREADS, SM_TOTAL * sizeof(float)>>>(x, wgt, bias, out);
}